// round 16
// baseline (speedup 1.0000x reference)
#include <cuda_runtime.h>
#include <cuda_bf16.h>

// GraphAttentionLayer: out = elu(softmax(h_j @ a_j + const) @ h_j)
// R11 structure (best: 21.5us) + packed f32x2 math (PTX fma.rn.f32x2 ->
// SASS FFMA2, sm_103a): dot + acc-update FMA count halved, same registers.
// Lane-remapped: warp = 4 row-groups x 8 lanes, lane owns a 16-dim slice
// -> 3 SHFLs per 4 rows. Online softmax w/ rare group-uniform rescale.
// __ldcg loads. Last-block-done finalize combines partials L2-hot.
// h_i . a_i is a constant logit shift -> cancels in softmax -> skipped.

#define D        128
#define NB       296          // 2 blocks/SM on 148 SMs
#define NT       512
#define WPB      (NT / 32)    // 16 warps
#define NW       (NB * WPB)   // 4736 warps
#define GRP      (NT / D)     // 4 finalize groups
#define NEGBIG   (-3.0e38f)

typedef unsigned long long u64;

__device__ float g_m[NB];
__device__ float g_s[NB];
__device__ float g_acc[NB * D];
__device__ unsigned int g_count;

__device__ __forceinline__ u64 fma2(u64 a, u64 b, u64 c) {
    u64 d; asm("fma.rn.f32x2 %0, %1, %2, %3;" : "=l"(d) : "l"(a), "l"(b), "l"(c)); return d;
}
__device__ __forceinline__ u64 mul2(u64 a, u64 b) {
    u64 d; asm("mul.rn.f32x2 %0, %1, %2;" : "=l"(d) : "l"(a), "l"(b)); return d;
}
__device__ __forceinline__ u64 pack2(float x) {
    u64 d; asm("mov.b64 %0, {%1, %1};" : "=l"(d) : "f"(x)); return d;
}
__device__ __forceinline__ float hsum2(u64 a) {
    float lo, hi; asm("mov.b64 {%0, %1}, %2;" : "=f"(lo), "=f"(hi) : "l"(a)); return lo + hi;
}

__global__ __launch_bounds__(NT, 2)
void gat_fused(const float* __restrict__ hj, const float* __restrict__ a,
               int nrows, float* __restrict__ out) {
    const int warp = threadIdx.x >> 5;
    const int lane = threadIdx.x & 31;
    const int grp  = lane >> 3;        // 0..3 : row within quad
    const int sub  = lane & 7;         // 0..7 : 16B piece within 128B line

    // lane's 16-dim slice of a_j as 8 packed f32x2
    __align__(16) float4 ajv[4];
    #pragma unroll
    for (int j = 0; j < 4; ++j)
        ajv[j] = *reinterpret_cast<const float4*>(a + D + j * 32 + sub * 4);
    const u64* aj2 = reinterpret_cast<const u64*>(ajv);

    const int gw    = blockIdx.x * WPB + warp;
    int chunk = (nrows + NW - 1) / NW;
    chunk = (chunk + 3) & ~3;                       // multiple of 4
    int r0 = gw * chunk;
    int r1 = r0 + chunk;
    if (r0 > nrows) r0 = nrows;
    if (r1 > nrows) r1 = nrows;
    const int n = r1 - r0;

    float m = -1e30f;
    float s = 0.0f;
    __align__(16) u64 acc2[8];         // 16 floats as 8 f32x2
    #pragma unroll
    for (int k = 0; k < 8; ++k) acc2[k] = 0ull;

    // base points at (row r0+grp, byte sub*16)
    const char* base = reinterpret_cast<const char*>(hj + (size_t)r0 * D)
                     + grp * 512 + sub * 16;

    for (int i = 0; i < n; i += 4) {
        const bool valid = (i + grp) < n;
        const char* p = base + (size_t)i * 512 - (valid ? 0 : grp * 512);

        __align__(16) float4 hv[4];
        hv[0] = __ldcg(reinterpret_cast<const float4*>(p));
        hv[1] = __ldcg(reinterpret_cast<const float4*>(p + 128));
        hv[2] = __ldcg(reinterpret_cast<const float4*>(p + 256));
        hv[3] = __ldcg(reinterpret_cast<const float4*>(p + 384));
        const u64* h2 = reinterpret_cast<const u64*>(hv);

        // dot: 8 packed FFMA2 (two 4-deep chains) + horizontal sum
        u64 t0 = mul2(h2[0], aj2[0]);
        u64 t1 = mul2(h2[1], aj2[1]);
        #pragma unroll
        for (int k = 1; k < 4; ++k) {
            t0 = fma2(h2[2 * k],     aj2[2 * k],     t0);
            t1 = fma2(h2[2 * k + 1], aj2[2 * k + 1], t1);
        }
        float d = hsum2(t0) + hsum2(t1);

        // reduce across the 8 lanes of this group: 3 SHFLs
        d += __shfl_xor_sync(0xffffffffu, d, 1);
        d += __shfl_xor_sync(0xffffffffu, d, 2);
        d += __shfl_xor_sync(0xffffffffu, d, 4);
        if (!valid) d = NEGBIG;                    // w -> 0

        if (d > m) {                                // group-uniform, rare
            float c = __expf(m - d);
            s *= c;
            u64 cc = pack2(c);
            #pragma unroll
            for (int k = 0; k < 8; ++k) acc2[k] = mul2(acc2[k], cc);
            m = d;
        }
        float w = __expf(d - m);
        s += w;
        u64 ww = pack2(w);
        #pragma unroll
        for (int k = 0; k < 8; ++k) acc2[k] = fma2(h2[k], ww, acc2[k]);
    }

    // unpack accumulator to float4 view for the combines
    float4* accf = reinterpret_cast<float4*>(acc2);

    // ---- Combine the 4 groups within the warp (xor 8, then 16) ----
    #pragma unroll
    for (int o = 8; o <= 16; o <<= 1) {
        float m2 = __shfl_xor_sync(0xffffffffu, m, o);
        float s2 = __shfl_xor_sync(0xffffffffu, s, o);
        float mn = fmaxf(m, m2);
        float c1 = __expf(m - mn);
        float c2 = __expf(m2 - mn);
        s = s * c1 + s2 * c2;
        #pragma unroll
        for (int j = 0; j < 4; ++j) {
            float4 a2;
            a2.x = __shfl_xor_sync(0xffffffffu, accf[j].x, o);
            a2.y = __shfl_xor_sync(0xffffffffu, accf[j].y, o);
            a2.z = __shfl_xor_sync(0xffffffffu, accf[j].z, o);
            a2.w = __shfl_xor_sync(0xffffffffu, accf[j].w, o);
            accf[j].x = accf[j].x * c1 + a2.x * c2;
            accf[j].y = accf[j].y * c1 + a2.y * c2;
            accf[j].z = accf[j].z * c1 + a2.z * c2;
            accf[j].w = accf[j].w * c1 + a2.w * c2;
        }
        m = mn;
    }
    // every lane now holds the warp partial for its sub's 16 dims

    // ---- Block combine in shared memory ----
    __shared__ float sm_m[WPB];
    __shared__ float sm_s[WPB];
    __shared__ __align__(16) float sm_acc[WPB][D];

    if (lane < 8) {
        #pragma unroll
        for (int j = 0; j < 4; ++j)
            *reinterpret_cast<float4*>(&sm_acc[warp][j * 32 + lane * 4]) = accf[j];
    }
    if (lane == 0) { sm_m[warp] = m; sm_s[warp] = s; }
    __syncthreads();

    if (threadIdx.x < D) {
        const int d = threadIdx.x;
        float M = -1e30f;
        #pragma unroll
        for (int w = 0; w < WPB; ++w) M = fmaxf(M, sm_m[w]);

        float st = 0.f, ad = 0.f;
        #pragma unroll
        for (int w = 0; w < WPB; ++w) {
            float c = __expf(sm_m[w] - M);
            st += sm_s[w] * c;
            ad += sm_acc[w][d] * c;
        }
        g_acc[blockIdx.x * D + d] = ad;
        if (d == 0) { g_m[blockIdx.x] = M; g_s[blockIdx.x] = st; }
    }

    // ---- Last-block-done finalize (partials L2-hot) ----
    __threadfence();
    __shared__ bool isLast;
    if (threadIdx.x == 0) {
        unsigned v = atomicAdd(&g_count, 1u);
        isLast = (v == NB - 1);
    }
    __syncthreads();
    if (!isLast) return;
    if (threadIdx.x == 0) g_count = 0;     // reset for graph replay

    const int t = threadIdx.x;
    __shared__ float red[WPB];
    __shared__ float sm_M, sm_S;
    __shared__ float sm_c[NB];
    __shared__ __align__(16) float sm_part[GRP][D];

    float mreg = (t < NB) ? __ldcg(&g_m[t]) : -1e30f;
    float mv = mreg;
    #pragma unroll
    for (int o = 16; o > 0; o >>= 1) mv = fmaxf(mv, __shfl_xor_sync(0xffffffffu, mv, o));
    if (lane == 0) red[warp] = mv;
    __syncthreads();
    if (t == 0) {
        float v = red[0];
        #pragma unroll
        for (int w = 1; w < WPB; ++w) v = fmaxf(v, red[w]);
        sm_M = v;
    }
    __syncthreads();
    const float M = sm_M;

    float sv = 0.f;
    if (t < NB) {
        float c = __expf(mreg - M);
        sm_c[t] = c;
        sv = __ldcg(&g_s[t]) * c;
    }
    #pragma unroll
    for (int o = 16; o > 0; o >>= 1) sv += __shfl_xor_sync(0xffffffffu, sv, o);
    __syncthreads();
    if (lane == 0) red[warp] = sv;
    __syncthreads();
    if (t == 0) {
        float v = 0.f;
        #pragma unroll
        for (int w = 0; w < WPB; ++w) v += red[w];
        sm_S = v;
    }
    __syncthreads();

    const int d  = t & (D - 1);
    const int fg = t >> 7;
    float ad = 0.f;
    for (int b = fg; b < NB; b += GRP)
        ad += __ldcg(&g_acc[b * D + d]) * sm_c[b];
    sm_part[fg][d] = ad;
    __syncthreads();

    if (t < D) {
        float total = 0.f;
        #pragma unroll
        for (int g = 0; g < GRP; ++g) total += sm_part[g][t];
        float h = total / sm_S;
        out[t] = (h > 0.f) ? h : expm1f(h);    // ELU, alpha = 1
    }
}

extern "C" void kernel_launch(void* const* d_in, const int* in_sizes, int n_in,
                              void* d_out, int out_size) {
    // inputs: [0] h_i (unused: constant logit shift cancels in softmax),
    //         [1] h_j [200000,128] f32, [2] a [256,1] f32
    const float* hj = (const float*)d_in[1];
    const float* a  = (const float*)d_in[2];
    const int nrows = in_sizes[1] / D;

    gat_fused<<<NB, NT>>>(hj, a, nrows, (float*)d_out);
}